// round 5
// baseline (speedup 1.0000x reference)
#include <cuda_runtime.h>

#define B 8
#define N 8192
#define D_INF 13
#define M 2048
#define K 32
#define NC (B*M)          /* 16384 centers */
#define NPAIR (NC/2)      /* 8192 */

/* output layout (floats): x_out, pos_s, batch_s */
#define X_OFF   0
#define P_OFF   (NC*128)
#define BA_OFF  (P_OFF + NC*3)

/* scratch (device globals; no allocation allowed) */
static __device__ int   g_fps_idx[NC];
static __device__ int   g_nbr[NC*K];
static __device__ int   g_nvalid[NC];
static __device__ float g_px[B*N];
static __device__ float g_py[B*N];
static __device__ float g_pz[B*N];
/* spatially sorted copies for FPS (original-index map in g_soi) */
static __device__ float g_spx[B*N];
static __device__ float g_spy[B*N];
static __device__ float g_spz[B*N];
static __device__ int   g_soi[B*N];

/* ---------------- packed f32x2 helpers (per-lane IEEE RN, bit-exact) ---- */
union F2U { unsigned long long u; float2 f; };

__device__ __forceinline__ unsigned long long pk2(float lo, float hi) {
    F2U c; c.f = make_float2(lo, hi); return c.u;
}
__device__ __forceinline__ float2 up2(unsigned long long v) {
    F2U c; c.u = v; return c.f;
}
__device__ __forceinline__ unsigned long long add2(unsigned long long a,
                                                   unsigned long long b) {
    unsigned long long r;
    asm("add.rn.f32x2 %0, %1, %2;" : "=l"(r) : "l"(a), "l"(b));
    return r;
}
__device__ __forceinline__ unsigned long long mul2(unsigned long long a,
                                                   unsigned long long b) {
    unsigned long long r;
    asm("mul.rn.f32x2 %0, %1, %2;" : "=l"(r) : "l"(a), "l"(b));
    return r;
}
__device__ __forceinline__ unsigned long long fma2(unsigned long long a,
                                                   unsigned long long b,
                                                   unsigned long long c) {
    unsigned long long r;
    asm("fma.rn.f32x2 %0, %1, %2, %3;" : "=l"(r) : "l"(a), "l"(b), "l"(c));
    return r;
}

/* ------------------------------------------------------------------ */
/* AoS -> SoA transpose of pos                                        */
/* ------------------------------------------------------------------ */
__global__ void soa_kernel(const float* __restrict__ pos) {
    int i = blockIdx.x * blockDim.x + threadIdx.x;
    if (i < B*N) {
        g_px[i] = pos[3*i + 0];
        g_py[i] = pos[3*i + 1];
        g_pz[i] = pos[3*i + 2];
    }
}

/* ------------------------------------------------------------------ */
/* Spatial bin sort (16 regions, 4x2x2 over [0,1)^3).                 */
/* Unstable placement is fine: FPS results depend only on per-point   */
/* D values and original indices, both placement-invariant.           */
/* ------------------------------------------------------------------ */
__device__ __forceinline__ int region_of(float x, float y, float z) {
    int rx = (int)(x * 4.0f); rx = rx < 0 ? 0 : (rx > 3 ? 3 : rx);
    int ry = (int)(y * 2.0f); ry = ry < 0 ? 0 : (ry > 1 ? 1 : ry);
    int rz = (int)(z * 2.0f); rz = rz < 0 ? 0 : (rz > 1 ? 1 : rz);
    return rx*4 + ry*2 + rz;
}

__global__ void __launch_bounds__(512) sort_kernel() {
    const int b = blockIdx.x, t = threadIdx.x;
    const int bN = b*N;
    __shared__ int hist[16];
    __shared__ int cursor[16];
    if (t < 16) hist[t] = 0;
    __syncthreads();
    for (int i = t; i < N; i += 512) {
        int r = region_of(g_px[bN+i], g_py[bN+i], g_pz[bN+i]);
        atomicAdd(&hist[r], 1);
    }
    __syncthreads();
    if (t == 0) {
        int acc = 0;
        for (int r = 0; r < 16; r++) { cursor[r] = acc; acc += hist[r]; }
    }
    __syncthreads();
    for (int i = t; i < N; i += 512) {
        float x = g_px[bN+i], y = g_py[bN+i], z = g_pz[bN+i];
        int r = region_of(x, y, z);
        int slot = atomicAdd(&cursor[r], 1);
        g_spx[bN+slot] = x;
        g_spy[bN+slot] = y;
        g_spz[bN+slot] = z;
        g_soi[bN+slot] = i;
    }
}

/* ------------------------------------------------------------------ */
/* FPS v3: one block/batch, 512 threads, 16 sorted pts/thread.        */
/* Per-warp bbox skip: warp update is a provable no-op when           */
/* lb^2(last,bbox)*(1-1e-3) >= warp maxD (cached REDUX key).          */
/* Skipped warps keep D / bv / skey[w] bit-identical -> exact result. */
/* ------------------------------------------------------------------ */
#define FPS_T 512

__global__ void __launch_bounds__(FPS_T, 1) fps_kernel() {
    const int b    = blockIdx.x;
    const int t    = threadIdx.x;
    const int w    = t >> 5;
    const int lane = t & 31;
    const int bN   = b*N;

    __shared__ unsigned skey[16];
    __shared__ int      swidx[2];

    unsigned long long X2[8], Y2[8], Z2[8];
    float D[16];
    int   oi[16];
    float mnx = 1e30f, mxx = -1e30f;
    float mny = 1e30f, mxy = -1e30f;
    float mnz = 1e30f, mxz = -1e30f;

#pragma unroll
    for (int u = 0; u < 8; u++) {
        int p0 = bN + t*16 + 2*u, p1 = p0 + 1;
        float x0 = g_spx[p0], x1 = g_spx[p1];
        float y0 = g_spy[p0], y1 = g_spy[p1];
        float z0 = g_spz[p0], z1 = g_spz[p1];
        X2[u] = pk2(x0, x1); Y2[u] = pk2(y0, y1); Z2[u] = pk2(z0, z1);
        oi[2*u]   = g_soi[p0];
        oi[2*u+1] = g_soi[p1];
        D[2*u] = 1e10f; D[2*u+1] = 1e10f;
        mnx = fminf(mnx, fminf(x0, x1)); mxx = fmaxf(mxx, fmaxf(x0, x1));
        mny = fminf(mny, fminf(y0, y1)); mxy = fmaxf(mxy, fmaxf(y0, y1));
        mnz = fminf(mnz, fminf(z0, z1)); mxz = fmaxf(mxz, fmaxf(z0, z1));
    }
    /* warp bbox: coords >= 0 -> float bits are order-preserving as u32 */
    mnx = __uint_as_float(__reduce_min_sync(0xffffffffu, __float_as_uint(mnx)));
    mxx = __uint_as_float(__reduce_max_sync(0xffffffffu, __float_as_uint(mxx)));
    mny = __uint_as_float(__reduce_min_sync(0xffffffffu, __float_as_uint(mny)));
    mxy = __uint_as_float(__reduce_max_sync(0xffffffffu, __float_as_uint(mxy)));
    mnz = __uint_as_float(__reduce_min_sync(0xffffffffu, __float_as_uint(mnz)));
    mxz = __uint_as_float(__reduce_max_sync(0xffffffffu, __float_as_uint(mxz)));

    if (t == 0) {
        g_fps_idx[b*M] = 0;
        swidx[0] = 0x7fffffff;
        swidx[1] = 0x7fffffff;
    }
    float wkeyf = 1e30f;         /* cached warp maxD (forces active at s=1) */
    float bv    = -1.0f;         /* cached per-lane maxD                    */
    int   last  = 0;
    __syncthreads();

    for (int s = 1; s < M; s++) {
        const int p = s & 1;
        const float lx = g_px[bN+last], ly = g_py[bN+last], lz = g_pz[bN+last];

        /* conservative lower bound on d(last, any point in warp bbox) */
        float ax = fmaxf(fmaxf(mnx - lx, lx - mxx), 0.0f);
        float ay = fmaxf(fmaxf(mny - ly, ly - mxy), 0.0f);
        float az = fmaxf(fmaxf(mnz - lz, lz - mxz), 0.0f);
        float lb2 = ax*ax + ay*ay + az*az;

        if (lb2 * 0.999f <= wkeyf) {      /* warp-uniform: no divergence */
            const unsigned long long nx = pk2(-lx, -lx);
            const unsigned long long ny = pk2(-ly, -ly);
            const unsigned long long nz = pk2(-lz, -lz);
#pragma unroll
            for (int u = 0; u < 8; u++) {
                unsigned long long dx = add2(X2[u], nx);
                unsigned long long dy = add2(Y2[u], ny);
                unsigned long long dz = add2(Z2[u], nz);
                /* match jnp: separate mul + left-to-right add, no FMA */
                unsigned long long d2 = add2(add2(mul2(dx,dx), mul2(dy,dy)),
                                             mul2(dz,dz));
                float2 dd = up2(d2);
                D[2*u]   = fminf(D[2*u],   dd.x);
                D[2*u+1] = fminf(D[2*u+1], dd.y);
            }
            float m = fmaxf(D[0], D[1]);
#pragma unroll
            for (int i = 2; i < 16; i++) m = fmaxf(m, D[i]);
            bv = m;
            unsigned wkeyb = __reduce_max_sync(0xffffffffu, __float_as_uint(bv));
            if (lane == 0) skey[w] = wkeyb;
            wkeyf = __uint_as_float(wkeyb);
        }
        __syncthreads();                                  /* bar 1 */

        if (t == 0) swidx[p ^ 1] = 0x7fffffff;            /* for step s+1 */

        unsigned v = (lane < 16) ? skey[lane] : 0u;
        const unsigned winb = __reduce_max_sync(0xffffffffu, v);

        if (__float_as_uint(bv) == winb) {                /* rare path */
            const float wf = __uint_as_float(winb);
            int cand = 0x7fffffff;
#pragma unroll
            for (int i = 0; i < 16; i++)
                if (D[i] == wf) cand = min(cand, oi[i]);  /* min ORIG idx */
            atomicMin(&swidx[p], cand);
        }
        __syncthreads();                                  /* bar 2 */

        last = swidx[p];
        if (t == 0) g_fps_idx[b*M + s] = last;
    }
}

/* ------------------------------------------------------------------ */
/* Ball query: one warp per center. First K in-ball points by index   */
/* via ballot + prefix popcount, early exit. Also emits pos_s/batch_s.*/
/* ------------------------------------------------------------------ */
__global__ void __launch_bounds__(256) ballquery_kernel(float* __restrict__ out) {
    const int w    = (blockIdx.x * 256 + threadIdx.x) >> 5;
    const int lane = threadIdx.x & 31;
    if (w >= NC) return;
    const int b = w >> 11;                 /* M = 2048 */

    const float* px = g_px + b*N;
    const float* py = g_py + b*N;
    const float* pz = g_pz + b*N;

    const int ci = g_fps_idx[w];
    const float cx = px[ci], cy = py[ci], cz = pz[ci];

    if (lane == 0) {
        out[P_OFF + 3*w + 0] = cx;
        out[P_OFF + 3*w + 1] = cy;
        out[P_OFF + 3*w + 2] = cz;
        out[BA_OFF + w]      = (float)b;   /* batch[b,n] == b */
    }

    int* nb = g_nbr + w*K;
    int cnt = 0;
    for (int base = 0; base < N; base += 32) {
        int n = base + lane;
        float dx = __fadd_rn(px[n], -cx);
        float dy = __fadd_rn(py[n], -cy);
        float dz = __fadd_rn(pz[n], -cz);
        float d  = __fadd_rn(__fadd_rn(__fmul_rn(dx,dx), __fmul_rn(dy,dy)),
                             __fmul_rn(dz,dz));
        bool in = (d <= 0.04f);            /* float32(0.04) == jnp's R*R cast  */
        unsigned msk = __ballot_sync(0xFFFFFFFFu, in);
        if (in) {
            int slot = cnt + __popc(msk & ((1u << lane) - 1u));
            if (slot < K) nb[slot] = n;
        }
        cnt += __popc(msk);
        if (cnt >= K) break;
    }
    int nv = cnt < K ? cnt : K;            /* >=1: center is in its own ball */
    for (int s2 = nv + lane; s2 < K; s2 += 32) nb[s2] = 0;  /* safe gather idx */
    if (lane == 0) g_nvalid[w] = nv;
}

/* ------------------------------------------------------------------ */
/* Fused gather + MLP(16->64->128) + masked max.                       */
/* Layer 2 uses FFMA2 (fma.rn.f32x2): h stored DUPLICATED in shared   */
/* as f32x2 pairs; W2 channel-pairs in register u64s -> 2 fp32 FMAs   */
/* per rt2 issue slot (2x fma-pipe throughput on the dominant layer). */
/* ------------------------------------------------------------------ */
#define SH2_PITCH 66   /* 64 + 2 u64 pad: staggers STS banks */

__global__ void __launch_bounds__(128, 2) mlp_kernel(
    const float* __restrict__ x,
    const float* __restrict__ W1, const float* __restrict__ b1,
    const float* __restrict__ W2, const float* __restrict__ b2,
    float* __restrict__ out)
{
    __shared__ float sW1[16][64];
    __shared__ float sb1[64];
    __shared__ unsigned long long sh2[2][32][SH2_PITCH]; /* dup'd h pairs */
    __shared__ int   s_nv[2];
    __shared__ int   s_nbr[2][32];
    __shared__ float s_cpos[2][3];

    const int t    = threadIdx.x;
    const int g    = t >> 6;               /* which center of the pair   */
    const int tp   = t & 63;               /* channel-pair id (0..63)    */
    const int kk   = (t >> 1) & 31;        /* neighbor for layer 1       */
    const int half = t & 1;                /* 32-channel half in layer 1 */

    for (int i = t; i < 16*64; i += 128) sW1[i >> 6][i & 63] = W1[i];
    if (t < 64) sb1[t] = b1[t];

    unsigned long long w2u[64];
#pragma unroll
    for (int j = 0; j < 64; j++) {
        float2 wv = *(const float2*)(W2 + j*128 + tp*2);
        w2u[j] = pk2(wv.x, wv.y);
    }
    const float2 b2v = *(const float2*)(b2 + tp*2);

    for (int pair = blockIdx.x; pair < NPAIR; pair += gridDim.x) {
        const int c = pair*2 + g;
        const int b = c >> 11;

        __syncthreads();                   /* protect sh2/s_* reuse */
        if (t < 2) {
            int cc = pair*2 + t;
            s_nv[t] = g_nvalid[cc];
            int ci  = g_fps_idx[cc];
            int bb  = cc >> 11;
            s_cpos[t][0] = g_px[bb*N + ci];
            s_cpos[t][1] = g_py[bb*N + ci];
            s_cpos[t][2] = g_pz[bb*N + ci];
        }
        if (t < 64) {
            int cc = pair*2 + (t >> 5);
            s_nbr[t >> 5][t & 31] = g_nbr[cc*K + (t & 31)];
        }
        __syncthreads();

        /* ---------- layer 1: feat(16) @ W1 -> relu -> sh2 (dup'd) -- */
        const int n  = s_nbr[g][kk];
        const int bn = b*N + n;
        float feat[16];
        const float* xr = x + (size_t)bn * D_INF;
#pragma unroll
        for (int j = 0; j < D_INF; j++) feat[j] = xr[j];
        feat[13] = g_px[bn] - s_cpos[g][0];
        feat[14] = g_py[bn] - s_cpos[g][1];
        feat[15] = g_pz[bn] - s_cpos[g][2];

#pragma unroll
        for (int ph = 0; ph < 2; ph++) {
            const int cbase = half*32 + ph*16;
            float hacc[16];
#pragma unroll
            for (int c2 = 0; c2 < 16; c2++) hacc[c2] = sb1[cbase + c2];
#pragma unroll
            for (int j = 0; j < 16; j++) {
                float f = feat[j];
#pragma unroll
                for (int c2 = 0; c2 < 16; c2++)
                    hacc[c2] = fmaf(f, sW1[j][cbase + c2], hacc[c2]);
            }
#pragma unroll
            for (int c2 = 0; c2 < 16; c2 += 2) {
                float v0 = fmaxf(hacc[c2+0], 0.f);
                float v1 = fmaxf(hacc[c2+1], 0.f);
                ulonglong2 v;
                v.x = pk2(v0, v0);
                v.y = pk2(v1, v1);
                *(ulonglong2*)&sh2[g][kk][cbase + c2] = v;   /* STS.128 */
            }
        }
        __syncthreads();

        /* ---------- layer 2: h @ W2 (FFMA2) -> max over k -> relu -- */
        const int nv = s_nv[g];
        float m0 = -3.4e38f, m1 = -3.4e38f;
        for (int k = 0; k < nv; k++) {
            const unsigned long long* hr = &sh2[g][k][0];
            unsigned long long a0 = 0ull, a1 = 0ull, a2 = 0ull, a3 = 0ull;
#pragma unroll
            for (int j = 0; j < 64; j += 4) {
                ulonglong2 h01 = *(const ulonglong2*)(hr + j);      /* bcast */
                ulonglong2 h23 = *(const ulonglong2*)(hr + j + 2);
                a0 = fma2(h01.x, w2u[j+0], a0);
                a1 = fma2(h01.y, w2u[j+1], a1);
                a2 = fma2(h23.x, w2u[j+2], a2);
                a3 = fma2(h23.y, w2u[j+3], a3);
            }
            unsigned long long ssum = add2(add2(a0, a1), add2(a2, a3));
            float2 dd = up2(ssum);
            m0 = fmaxf(m0, dd.x);
            m1 = fmaxf(m1, dd.y);
        }
        /* relu(max_k(dot)+b2) == max_k(relu(dot+b2)): relu monotone,
           and at least one valid neighbor always exists */
        float2 o;
        o.x = fmaxf(m0 + b2v.x, 0.f);
        o.y = fmaxf(m1 + b2v.y, 0.f);
        *(float2*)(out + X_OFF + (size_t)c*128 + tp*2) = o;
    }
}

/* ------------------------------------------------------------------ */
extern "C" void kernel_launch(void* const* d_in, const int* in_sizes, int n_in,
                              void* d_out, int out_size) {
    const float* x   = (const float*)d_in[0];
    const float* pos = (const float*)d_in[1];
    /* d_in[2] = batch (int32), values are just the batch index: unused */
    const float* W1  = (const float*)d_in[3];
    const float* b1  = (const float*)d_in[4];
    const float* W2  = (const float*)d_in[5];
    const float* b2  = (const float*)d_in[6];
    float* out = (float*)d_out;

    soa_kernel<<<(B*N + 255)/256, 256>>>(pos);
    sort_kernel<<<B, 512>>>();
    fps_kernel<<<B, FPS_T>>>();
    ballquery_kernel<<<(NC*32)/256, 256>>>(out);
    mlp_kernel<<<296, 128>>>(x, W1, b1, W2, b2, out);
}

// round 7
// speedup vs baseline: 1.0046x; 1.0046x over previous
#include <cuda_runtime.h>

#define B 8
#define N 8192
#define D_INF 13
#define M 2048
#define K 32
#define NC (B*M)          /* 16384 centers */
#define NPAIR (NC/2)      /* 8192 */

/* output layout (floats): x_out, pos_s, batch_s */
#define X_OFF   0
#define P_OFF   (NC*128)
#define BA_OFF  (P_OFF + NC*3)

/* scratch (device globals; no allocation allowed) */
static __device__ int   g_fps_idx[NC];
static __device__ int   g_nbr[NC*K];
static __device__ int   g_nvalid[NC];
static __device__ float g_px[B*N];
static __device__ float g_py[B*N];
static __device__ float g_pz[B*N];
/* spatially sorted copies for FPS (original-index map in g_soi) */
static __device__ float g_spx[B*N];
static __device__ float g_spy[B*N];
static __device__ float g_spz[B*N];
static __device__ int   g_soi[B*N];

/* ---------------- packed f32x2 helpers (per-lane IEEE RN, bit-exact) ---- */
union F2U { unsigned long long u; float2 f; };

__device__ __forceinline__ unsigned long long pk2(float lo, float hi) {
    F2U c; c.f = make_float2(lo, hi); return c.u;
}
__device__ __forceinline__ float2 up2(unsigned long long v) {
    F2U c; c.u = v; return c.f;
}
__device__ __forceinline__ unsigned long long add2(unsigned long long a,
                                                   unsigned long long b) {
    unsigned long long r;
    asm("add.rn.f32x2 %0, %1, %2;" : "=l"(r) : "l"(a), "l"(b));
    return r;
}
__device__ __forceinline__ unsigned long long mul2(unsigned long long a,
                                                   unsigned long long b) {
    unsigned long long r;
    asm("mul.rn.f32x2 %0, %1, %2;" : "=l"(r) : "l"(a), "l"(b));
    return r;
}
__device__ __forceinline__ unsigned long long fma2(unsigned long long a,
                                                   unsigned long long b,
                                                   unsigned long long c) {
    unsigned long long r;
    asm("fma.rn.f32x2 %0, %1, %2, %3;" : "=l"(r) : "l"(a), "l"(b), "l"(c));
    return r;
}

/* ------------------------------------------------------------------ */
/* AoS -> SoA transpose of pos                                        */
/* ------------------------------------------------------------------ */
__global__ void soa_kernel(const float* __restrict__ pos) {
    int i = blockIdx.x * blockDim.x + threadIdx.x;
    if (i < B*N) {
        g_px[i] = pos[3*i + 0];
        g_py[i] = pos[3*i + 1];
        g_pz[i] = pos[3*i + 2];
    }
}

/* ------------------------------------------------------------------ */
/* Spatial bin sort (16 regions, 4x2x2 over [0,1)^3).                 */
/* Unstable placement is fine: FPS results depend only on per-point   */
/* D values and original indices, both placement-invariant.           */
/* ------------------------------------------------------------------ */
__device__ __forceinline__ int region_of(float x, float y, float z) {
    int rx = (int)(x * 4.0f); rx = rx < 0 ? 0 : (rx > 3 ? 3 : rx);
    int ry = (int)(y * 2.0f); ry = ry < 0 ? 0 : (ry > 1 ? 1 : ry);
    int rz = (int)(z * 2.0f); rz = rz < 0 ? 0 : (rz > 1 ? 1 : rz);
    return rx*4 + ry*2 + rz;
}

__global__ void __launch_bounds__(512) sort_kernel() {
    const int b = blockIdx.x, t = threadIdx.x;
    const int bN = b*N;
    __shared__ int hist[16];
    __shared__ int cursor[16];
    if (t < 16) hist[t] = 0;
    __syncthreads();
    for (int i = t; i < N; i += 512) {
        int r = region_of(g_px[bN+i], g_py[bN+i], g_pz[bN+i]);
        atomicAdd(&hist[r], 1);
    }
    __syncthreads();
    if (t == 0) {
        int acc = 0;
        for (int r = 0; r < 16; r++) { cursor[r] = acc; acc += hist[r]; }
    }
    __syncthreads();
    for (int i = t; i < N; i += 512) {
        float x = g_px[bN+i], y = g_py[bN+i], z = g_pz[bN+i];
        int r = region_of(x, y, z);
        int slot = atomicAdd(&cursor[r], 1);
        g_spx[bN+slot] = x;
        g_spy[bN+slot] = y;
        g_spz[bN+slot] = z;
        g_soi[bN+slot] = i;
    }
}

/* ------------------------------------------------------------------ */
/* FPS v3: one block/batch, 512 threads, 16 sorted pts/thread.        */
/* Per-warp bbox skip: warp update is a provable no-op when           */
/* lb^2(last,bbox)*(1-1e-3) >= warp maxD (cached REDUX key).          */
/* Skipped warps keep D / bv / skey[w] bit-identical -> exact result. */
/* ------------------------------------------------------------------ */
#define FPS_T 512

__global__ void __launch_bounds__(FPS_T, 1) fps_kernel() {
    const int b    = blockIdx.x;
    const int t    = threadIdx.x;
    const int w    = t >> 5;
    const int lane = t & 31;
    const int bN   = b*N;

    __shared__ unsigned skey[16];
    __shared__ int      swidx[2];

    unsigned long long X2[8], Y2[8], Z2[8];
    float D[16];
    int   oi[16];
    float mnx = 1e30f, mxx = -1e30f;
    float mny = 1e30f, mxy = -1e30f;
    float mnz = 1e30f, mxz = -1e30f;

#pragma unroll
    for (int u = 0; u < 8; u++) {
        int p0 = bN + t*16 + 2*u, p1 = p0 + 1;
        float x0 = g_spx[p0], x1 = g_spx[p1];
        float y0 = g_spy[p0], y1 = g_spy[p1];
        float z0 = g_spz[p0], z1 = g_spz[p1];
        X2[u] = pk2(x0, x1); Y2[u] = pk2(y0, y1); Z2[u] = pk2(z0, z1);
        oi[2*u]   = g_soi[p0];
        oi[2*u+1] = g_soi[p1];
        D[2*u] = 1e10f; D[2*u+1] = 1e10f;
        mnx = fminf(mnx, fminf(x0, x1)); mxx = fmaxf(mxx, fmaxf(x0, x1));
        mny = fminf(mny, fminf(y0, y1)); mxy = fmaxf(mxy, fmaxf(y0, y1));
        mnz = fminf(mnz, fminf(z0, z1)); mxz = fmaxf(mxz, fmaxf(z0, z1));
    }
    /* warp bbox: coords >= 0 -> float bits are order-preserving as u32 */
    mnx = __uint_as_float(__reduce_min_sync(0xffffffffu, __float_as_uint(mnx)));
    mxx = __uint_as_float(__reduce_max_sync(0xffffffffu, __float_as_uint(mxx)));
    mny = __uint_as_float(__reduce_min_sync(0xffffffffu, __float_as_uint(mny)));
    mxy = __uint_as_float(__reduce_max_sync(0xffffffffu, __float_as_uint(mxy)));
    mnz = __uint_as_float(__reduce_min_sync(0xffffffffu, __float_as_uint(mnz)));
    mxz = __uint_as_float(__reduce_max_sync(0xffffffffu, __float_as_uint(mxz)));

    if (t == 0) {
        g_fps_idx[b*M] = 0;
        swidx[0] = 0x7fffffff;
        swidx[1] = 0x7fffffff;
    }
    float wkeyf = 1e30f;         /* cached warp maxD (forces active at s=1) */
    float bv    = -1.0f;         /* cached per-lane maxD                    */
    int   last  = 0;
    __syncthreads();

    for (int s = 1; s < M; s++) {
        const int p = s & 1;
        const float lx = g_px[bN+last], ly = g_py[bN+last], lz = g_pz[bN+last];

        /* conservative lower bound on d(last, any point in warp bbox) */
        float ax = fmaxf(fmaxf(mnx - lx, lx - mxx), 0.0f);
        float ay = fmaxf(fmaxf(mny - ly, ly - mxy), 0.0f);
        float az = fmaxf(fmaxf(mnz - lz, lz - mxz), 0.0f);
        float lb2 = ax*ax + ay*ay + az*az;

        if (lb2 * 0.999f <= wkeyf) {      /* warp-uniform: no divergence */
            const unsigned long long nx = pk2(-lx, -lx);
            const unsigned long long ny = pk2(-ly, -ly);
            const unsigned long long nz = pk2(-lz, -lz);
#pragma unroll
            for (int u = 0; u < 8; u++) {
                unsigned long long dx = add2(X2[u], nx);
                unsigned long long dy = add2(Y2[u], ny);
                unsigned long long dz = add2(Z2[u], nz);
                /* match jnp: separate mul + left-to-right add, no FMA */
                unsigned long long d2 = add2(add2(mul2(dx,dx), mul2(dy,dy)),
                                             mul2(dz,dz));
                float2 dd = up2(d2);
                D[2*u]   = fminf(D[2*u],   dd.x);
                D[2*u+1] = fminf(D[2*u+1], dd.y);
            }
            float m = fmaxf(D[0], D[1]);
#pragma unroll
            for (int i = 2; i < 16; i++) m = fmaxf(m, D[i]);
            bv = m;
            unsigned wkeyb = __reduce_max_sync(0xffffffffu, __float_as_uint(bv));
            if (lane == 0) skey[w] = wkeyb;
            wkeyf = __uint_as_float(wkeyb);
        }
        __syncthreads();                                  /* bar 1 */

        if (t == 0) swidx[p ^ 1] = 0x7fffffff;            /* for step s+1 */

        unsigned v = (lane < 16) ? skey[lane] : 0u;
        const unsigned winb = __reduce_max_sync(0xffffffffu, v);

        if (__float_as_uint(bv) == winb) {                /* rare path */
            const float wf = __uint_as_float(winb);
            int cand = 0x7fffffff;
#pragma unroll
            for (int i = 0; i < 16; i++)
                if (D[i] == wf) cand = min(cand, oi[i]);  /* min ORIG idx */
            atomicMin(&swidx[p], cand);
        }
        __syncthreads();                                  /* bar 2 */

        last = swidx[p];
        if (t == 0) g_fps_idx[b*M + s] = last;
    }
}

/* ------------------------------------------------------------------ */
/* Ball query: one warp per center. First K in-ball points by index   */
/* via ballot + prefix popcount, early exit. Also emits pos_s/batch_s.*/
/* ------------------------------------------------------------------ */
__global__ void __launch_bounds__(256) ballquery_kernel(float* __restrict__ out) {
    const int w    = (blockIdx.x * 256 + threadIdx.x) >> 5;
    const int lane = threadIdx.x & 31;
    if (w >= NC) return;
    const int b = w >> 11;                 /* M = 2048 */

    const float* px = g_px + b*N;
    const float* py = g_py + b*N;
    const float* pz = g_pz + b*N;

    const int ci = g_fps_idx[w];
    const float cx = px[ci], cy = py[ci], cz = pz[ci];

    if (lane == 0) {
        out[P_OFF + 3*w + 0] = cx;
        out[P_OFF + 3*w + 1] = cy;
        out[P_OFF + 3*w + 2] = cz;
        out[BA_OFF + w]      = (float)b;   /* batch[b,n] == b */
    }

    int* nb = g_nbr + w*K;
    int cnt = 0;
    for (int base = 0; base < N; base += 32) {
        int n = base + lane;
        float dx = __fadd_rn(px[n], -cx);
        float dy = __fadd_rn(py[n], -cy);
        float dz = __fadd_rn(pz[n], -cz);
        float d  = __fadd_rn(__fadd_rn(__fmul_rn(dx,dx), __fmul_rn(dy,dy)),
                             __fmul_rn(dz,dz));
        bool in = (d <= 0.04f);            /* float32(0.04) == jnp's R*R cast  */
        unsigned msk = __ballot_sync(0xFFFFFFFFu, in);
        if (in) {
            int slot = cnt + __popc(msk & ((1u << lane) - 1u));
            if (slot < K) nb[slot] = n;
        }
        cnt += __popc(msk);
        if (cnt >= K) break;
    }
    int nv = cnt < K ? cnt : K;            /* >=1: center is in its own ball */
    for (int s2 = nv + lane; s2 < K; s2 += 32) nb[s2] = 0;  /* safe gather idx */
    if (lane == 0) g_nvalid[w] = nv;
}

/* ------------------------------------------------------------------ */
/* Fused gather + MLP(16->64->128) + masked max.                       */
/* Layer 2 uses FFMA2 (fma.rn.f32x2): h stored DUPLICATED in shared   */
/* as f32x2 pairs; W2 channel-pairs in register u64s -> 2 fp32 FMAs   */
/* per rt2 issue slot (2x fma-pipe throughput on the dominant layer). */
/* ------------------------------------------------------------------ */
#define SH2_PITCH 66   /* 64 + 2 u64 pad: staggers STS banks */

__global__ void __launch_bounds__(128, 2) mlp_kernel(
    const float* __restrict__ x,
    const float* __restrict__ W1, const float* __restrict__ b1,
    const float* __restrict__ W2, const float* __restrict__ b2,
    float* __restrict__ out)
{
    __shared__ float sW1[16][64];
    __shared__ float sb1[64];
    __shared__ unsigned long long sh2[2][32][SH2_PITCH]; /* dup'd h pairs */
    __shared__ int   s_nv[2];
    __shared__ int   s_nbr[2][32];
    __shared__ float s_cpos[2][3];

    const int t    = threadIdx.x;
    const int g    = t >> 6;               /* which center of the pair   */
    const int tp   = t & 63;               /* channel-pair id (0..63)    */
    const int kk   = (t >> 1) & 31;        /* neighbor for layer 1       */
    const int half = t & 1;                /* 32-channel half in layer 1 */

    for (int i = t; i < 16*64; i += 128) sW1[i >> 6][i & 63] = W1[i];
    if (t < 64) sb1[t] = b1[t];

    unsigned long long w2u[64];
#pragma unroll
    for (int j = 0; j < 64; j++) {
        float2 wv = *(const float2*)(W2 + j*128 + tp*2);
        w2u[j] = pk2(wv.x, wv.y);
    }
    const float2 b2v = *(const float2*)(b2 + tp*2);

    for (int pair = blockIdx.x; pair < NPAIR; pair += gridDim.x) {
        const int c = pair*2 + g;
        const int b = c >> 11;

        __syncthreads();                   /* protect sh2/s_* reuse */
        if (t < 2) {
            int cc = pair*2 + t;
            s_nv[t] = g_nvalid[cc];
            int ci  = g_fps_idx[cc];
            int bb  = cc >> 11;
            s_cpos[t][0] = g_px[bb*N + ci];
            s_cpos[t][1] = g_py[bb*N + ci];
            s_cpos[t][2] = g_pz[bb*N + ci];
        }
        if (t < 64) {
            int cc = pair*2 + (t >> 5);
            s_nbr[t >> 5][t & 31] = g_nbr[cc*K + (t & 31)];
        }
        __syncthreads();

        /* ---------- layer 1: feat(16) @ W1 -> relu -> sh2 (dup'd) -- */
        const int n  = s_nbr[g][kk];
        const int bn = b*N + n;
        float feat[16];
        const float* xr = x + (size_t)bn * D_INF;
#pragma unroll
        for (int j = 0; j < D_INF; j++) feat[j] = xr[j];
        feat[13] = g_px[bn] - s_cpos[g][0];
        feat[14] = g_py[bn] - s_cpos[g][1];
        feat[15] = g_pz[bn] - s_cpos[g][2];

#pragma unroll
        for (int ph = 0; ph < 2; ph++) {
            const int cbase = half*32 + ph*16;
            float hacc[16];
#pragma unroll
            for (int c2 = 0; c2 < 16; c2++) hacc[c2] = sb1[cbase + c2];
#pragma unroll
            for (int j = 0; j < 16; j++) {
                float f = feat[j];
#pragma unroll
                for (int c2 = 0; c2 < 16; c2++)
                    hacc[c2] = fmaf(f, sW1[j][cbase + c2], hacc[c2]);
            }
#pragma unroll
            for (int c2 = 0; c2 < 16; c2 += 2) {
                float v0 = fmaxf(hacc[c2+0], 0.f);
                float v1 = fmaxf(hacc[c2+1], 0.f);
                ulonglong2 v;
                v.x = pk2(v0, v0);
                v.y = pk2(v1, v1);
                *(ulonglong2*)&sh2[g][kk][cbase + c2] = v;   /* STS.128 */
            }
        }
        __syncthreads();

        /* ---------- layer 2: h @ W2 (FFMA2) -> max over k -> relu -- */
        const int nv = s_nv[g];
        float m0 = -3.4e38f, m1 = -3.4e38f;
        for (int k = 0; k < nv; k++) {
            const unsigned long long* hr = &sh2[g][k][0];
            unsigned long long a0 = 0ull, a1 = 0ull, a2 = 0ull, a3 = 0ull;
#pragma unroll
            for (int j = 0; j < 64; j += 4) {
                ulonglong2 h01 = *(const ulonglong2*)(hr + j);      /* bcast */
                ulonglong2 h23 = *(const ulonglong2*)(hr + j + 2);
                a0 = fma2(h01.x, w2u[j+0], a0);
                a1 = fma2(h01.y, w2u[j+1], a1);
                a2 = fma2(h23.x, w2u[j+2], a2);
                a3 = fma2(h23.y, w2u[j+3], a3);
            }
            unsigned long long ssum = add2(add2(a0, a1), add2(a2, a3));
            float2 dd = up2(ssum);
            m0 = fmaxf(m0, dd.x);
            m1 = fmaxf(m1, dd.y);
        }
        /* relu(max_k(dot)+b2) == max_k(relu(dot+b2)): relu monotone,
           and at least one valid neighbor always exists */
        float2 o;
        o.x = fmaxf(m0 + b2v.x, 0.f);
        o.y = fmaxf(m1 + b2v.y, 0.f);
        *(float2*)(out + X_OFF + (size_t)c*128 + tp*2) = o;
    }
}

/* ------------------------------------------------------------------ */
extern "C" void kernel_launch(void* const* d_in, const int* in_sizes, int n_in,
                              void* d_out, int out_size) {
    const float* x   = (const float*)d_in[0];
    const float* pos = (const float*)d_in[1];
    /* d_in[2] = batch (int32), values are just the batch index: unused */
    const float* W1  = (const float*)d_in[3];
    const float* b1  = (const float*)d_in[4];
    const float* W2  = (const float*)d_in[5];
    const float* b2  = (const float*)d_in[6];
    float* out = (float*)d_out;

    soa_kernel<<<(B*N + 255)/256, 256>>>(pos);
    sort_kernel<<<B, 512>>>();
    fps_kernel<<<B, FPS_T>>>();
    ballquery_kernel<<<(NC*32)/256, 256>>>(out);
    mlp_kernel<<<296, 128>>>(x, W1, b1, W2, b2, out);
}

// round 11
// speedup vs baseline: 1.0453x; 1.0405x over previous
#include <cuda_runtime.h>

#define B 8
#define N 8192
#define D_INF 13
#define M 2048
#define K 32
#define NC (B*M)          /* 16384 centers */
#define NPAIR (NC/2)      /* 8192 */

/* output layout (floats): x_out, pos_s, batch_s */
#define X_OFF   0
#define P_OFF   (NC*128)
#define BA_OFF  (P_OFF + NC*3)

/* scratch (device globals; no allocation allowed) */
static __device__ int   g_fps_idx[NC];
static __device__ int   g_nbr[NC*K];
static __device__ int   g_nvalid[NC];
static __device__ float g_px[B*N];
static __device__ float g_py[B*N];
static __device__ float g_pz[B*N];
/* spatially sorted copies for FPS (original-index map in g_soi) */
static __device__ float g_spx[B*N];
static __device__ float g_spy[B*N];
static __device__ float g_spz[B*N];
static __device__ int   g_soi[B*N];

/* ---------------- packed f32x2 helpers (per-lane IEEE RN, bit-exact) ---- */
union F2U { unsigned long long u; float2 f; };

__device__ __forceinline__ unsigned long long pk2(float lo, float hi) {
    F2U c; c.f = make_float2(lo, hi); return c.u;
}
__device__ __forceinline__ float2 up2(unsigned long long v) {
    F2U c; c.u = v; return c.f;
}
__device__ __forceinline__ unsigned long long add2(unsigned long long a,
                                                   unsigned long long b) {
    unsigned long long r;
    asm("add.rn.f32x2 %0, %1, %2;" : "=l"(r) : "l"(a), "l"(b));
    return r;
}
__device__ __forceinline__ unsigned long long mul2(unsigned long long a,
                                                   unsigned long long b) {
    unsigned long long r;
    asm("mul.rn.f32x2 %0, %1, %2;" : "=l"(r) : "l"(a), "l"(b));
    return r;
}

/* ------------------------------------------------------------------ */
/* AoS -> SoA transpose of pos                                        */
/* ------------------------------------------------------------------ */
__global__ void soa_kernel(const float* __restrict__ pos) {
    int i = blockIdx.x * blockDim.x + threadIdx.x;
    if (i < B*N) {
        g_px[i] = pos[3*i + 0];
        g_py[i] = pos[3*i + 1];
        g_pz[i] = pos[3*i + 2];
    }
}

/* ------------------------------------------------------------------ */
/* Spatial bin sort (16 regions, 4x2x2 over [0,1)^3).                 */
/* Unstable placement is fine: FPS results depend only on per-point   */
/* D values and original indices, both placement-invariant.           */
/* ------------------------------------------------------------------ */
__device__ __forceinline__ int region_of(float x, float y, float z) {
    int rx = (int)(x * 4.0f); rx = rx < 0 ? 0 : (rx > 3 ? 3 : rx);
    int ry = (int)(y * 2.0f); ry = ry < 0 ? 0 : (ry > 1 ? 1 : ry);
    int rz = (int)(z * 2.0f); rz = rz < 0 ? 0 : (rz > 1 ? 1 : rz);
    return rx*4 + ry*2 + rz;
}

__global__ void __launch_bounds__(512) sort_kernel() {
    const int b = blockIdx.x, t = threadIdx.x;
    const int bN = b*N;
    __shared__ int hist[16];
    __shared__ int cursor[16];
    if (t < 16) hist[t] = 0;
    __syncthreads();
    for (int i = t; i < N; i += 512) {
        int r = region_of(g_px[bN+i], g_py[bN+i], g_pz[bN+i]);
        atomicAdd(&hist[r], 1);
    }
    __syncthreads();
    if (t == 0) {
        int acc = 0;
        for (int r = 0; r < 16; r++) { cursor[r] = acc; acc += hist[r]; }
    }
    __syncthreads();
    for (int i = t; i < N; i += 512) {
        float x = g_px[bN+i], y = g_py[bN+i], z = g_pz[bN+i];
        int r = region_of(x, y, z);
        int slot = atomicAdd(&cursor[r], 1);
        g_spx[bN+slot] = x;
        g_spy[bN+slot] = y;
        g_spz[bN+slot] = z;
        g_soi[bN+slot] = i;
    }
}

/* ------------------------------------------------------------------ */
/* FPS v3: one block/batch, 512 threads, 16 sorted pts/thread.        */
/* Per-warp bbox skip: warp update is a provable no-op when           */
/* lb^2(last,bbox)*(1-1e-3) >= warp maxD (cached REDUX key).          */
/* Skipped warps keep D / bv / skey[w] bit-identical -> exact result. */
/* ------------------------------------------------------------------ */
#define FPS_T 512

__global__ void __launch_bounds__(FPS_T, 1) fps_kernel() {
    const int b    = blockIdx.x;
    const int t    = threadIdx.x;
    const int w    = t >> 5;
    const int lane = t & 31;
    const int bN   = b*N;

    __shared__ unsigned skey[16];
    __shared__ int      swidx[2];

    unsigned long long X2[8], Y2[8], Z2[8];
    float D[16];
    int   oi[16];
    float mnx = 1e30f, mxx = -1e30f;
    float mny = 1e30f, mxy = -1e30f;
    float mnz = 1e30f, mxz = -1e30f;

#pragma unroll
    for (int u = 0; u < 8; u++) {
        int p0 = bN + t*16 + 2*u, p1 = p0 + 1;
        float x0 = g_spx[p0], x1 = g_spx[p1];
        float y0 = g_spy[p0], y1 = g_spy[p1];
        float z0 = g_spz[p0], z1 = g_spz[p1];
        X2[u] = pk2(x0, x1); Y2[u] = pk2(y0, y1); Z2[u] = pk2(z0, z1);
        oi[2*u]   = g_soi[p0];
        oi[2*u+1] = g_soi[p1];
        D[2*u] = 1e10f; D[2*u+1] = 1e10f;
        mnx = fminf(mnx, fminf(x0, x1)); mxx = fmaxf(mxx, fmaxf(x0, x1));
        mny = fminf(mny, fminf(y0, y1)); mxy = fmaxf(mxy, fmaxf(y0, y1));
        mnz = fminf(mnz, fminf(z0, z1)); mxz = fmaxf(mxz, fmaxf(z0, z1));
    }
    /* warp bbox: coords >= 0 -> float bits are order-preserving as u32 */
    mnx = __uint_as_float(__reduce_min_sync(0xffffffffu, __float_as_uint(mnx)));
    mxx = __uint_as_float(__reduce_max_sync(0xffffffffu, __float_as_uint(mxx)));
    mny = __uint_as_float(__reduce_min_sync(0xffffffffu, __float_as_uint(mny)));
    mxy = __uint_as_float(__reduce_max_sync(0xffffffffu, __float_as_uint(mxy)));
    mnz = __uint_as_float(__reduce_min_sync(0xffffffffu, __float_as_uint(mnz)));
    mxz = __uint_as_float(__reduce_max_sync(0xffffffffu, __float_as_uint(mxz)));

    if (t == 0) {
        g_fps_idx[b*M] = 0;
        swidx[0] = 0x7fffffff;
        swidx[1] = 0x7fffffff;
    }
    float wkeyf = 1e30f;         /* cached warp maxD (forces active at s=1) */
    float bv    = -1.0f;         /* cached per-lane maxD                    */
    int   last  = 0;
    __syncthreads();

    for (int s = 1; s < M; s++) {
        const int p = s & 1;
        const float lx = g_px[bN+last], ly = g_py[bN+last], lz = g_pz[bN+last];

        /* conservative lower bound on d(last, any point in warp bbox) */
        float ax = fmaxf(fmaxf(mnx - lx, lx - mxx), 0.0f);
        float ay = fmaxf(fmaxf(mny - ly, ly - mxy), 0.0f);
        float az = fmaxf(fmaxf(mnz - lz, lz - mxz), 0.0f);
        float lb2 = ax*ax + ay*ay + az*az;

        if (lb2 * 0.999f <= wkeyf) {      /* warp-uniform: no divergence */
            const unsigned long long nx = pk2(-lx, -lx);
            const unsigned long long ny = pk2(-ly, -ly);
            const unsigned long long nz = pk2(-lz, -lz);
#pragma unroll
            for (int u = 0; u < 8; u++) {
                unsigned long long dx = add2(X2[u], nx);
                unsigned long long dy = add2(Y2[u], ny);
                unsigned long long dz = add2(Z2[u], nz);
                /* match jnp: separate mul + left-to-right add, no FMA */
                unsigned long long d2 = add2(add2(mul2(dx,dx), mul2(dy,dy)),
                                             mul2(dz,dz));
                float2 dd = up2(d2);
                D[2*u]   = fminf(D[2*u],   dd.x);
                D[2*u+1] = fminf(D[2*u+1], dd.y);
            }
            float m = fmaxf(D[0], D[1]);
#pragma unroll
            for (int i = 2; i < 16; i++) m = fmaxf(m, D[i]);
            bv = m;
            unsigned wkeyb = __reduce_max_sync(0xffffffffu, __float_as_uint(bv));
            if (lane == 0) skey[w] = wkeyb;
            wkeyf = __uint_as_float(wkeyb);
        }
        __syncthreads();                                  /* bar 1 */

        if (t == 0) swidx[p ^ 1] = 0x7fffffff;            /* for step s+1 */

        unsigned v = (lane < 16) ? skey[lane] : 0u;
        const unsigned winb = __reduce_max_sync(0xffffffffu, v);

        if (__float_as_uint(bv) == winb) {                /* rare path */
            const float wf = __uint_as_float(winb);
            int cand = 0x7fffffff;
#pragma unroll
            for (int i = 0; i < 16; i++)
                if (D[i] == wf) cand = min(cand, oi[i]);  /* min ORIG idx */
            atomicMin(&swidx[p], cand);
        }
        __syncthreads();                                  /* bar 2 */

        last = swidx[p];
        if (t == 0) g_fps_idx[b*M + s] = last;
    }
}

/* ------------------------------------------------------------------ */
/* Ball query: one warp per center. First K in-ball points by index   */
/* via ballot + prefix popcount, early exit. Also emits pos_s/batch_s.*/
/* ------------------------------------------------------------------ */
__global__ void __launch_bounds__(256) ballquery_kernel(float* __restrict__ out) {
    const int w    = (blockIdx.x * 256 + threadIdx.x) >> 5;
    const int lane = threadIdx.x & 31;
    if (w >= NC) return;
    const int b = w >> 11;                 /* M = 2048 */

    const float* px = g_px + b*N;
    const float* py = g_py + b*N;
    const float* pz = g_pz + b*N;

    const int ci = g_fps_idx[w];
    const float cx = px[ci], cy = py[ci], cz = pz[ci];

    if (lane == 0) {
        out[P_OFF + 3*w + 0] = cx;
        out[P_OFF + 3*w + 1] = cy;
        out[P_OFF + 3*w + 2] = cz;
        out[BA_OFF + w]      = (float)b;   /* batch[b,n] == b */
    }

    int* nb = g_nbr + w*K;
    int cnt = 0;
    for (int base = 0; base < N; base += 32) {
        int n = base + lane;
        float dx = __fadd_rn(px[n], -cx);
        float dy = __fadd_rn(py[n], -cy);
        float dz = __fadd_rn(pz[n], -cz);
        float d  = __fadd_rn(__fadd_rn(__fmul_rn(dx,dx), __fmul_rn(dy,dy)),
                             __fmul_rn(dz,dz));
        bool in = (d <= 0.04f);            /* float32(0.04) == jnp's R*R cast  */
        unsigned msk = __ballot_sync(0xFFFFFFFFu, in);
        if (in) {
            int slot = cnt + __popc(msk & ((1u << lane) - 1u));
            if (slot < K) nb[slot] = n;
        }
        cnt += __popc(msk);
        if (cnt >= K) break;
    }
    int nv = cnt < K ? cnt : K;            /* >=1: center is in its own ball */
    for (int s2 = nv + lane; s2 < K; s2 += 32) nb[s2] = 0;  /* safe gather idx */
    if (lane == 0) g_nvalid[w] = nv;
}

/* ------------------------------------------------------------------ */
/* Fused gather + MLP(16->64->128) + masked max.  (R4 proven version) */
/* Block = 128 threads handles 2 centers per iteration.               */
/*   warps 0,1 -> center g=0 ; warps 2,3 -> center g=1                */
/*   thread owns 2 output channels (W2 columns live in 128 registers) */
/*   h[32][64] per center lives in shared (broadcast LDS.128 reads)   */
/* Grid-stride so W2 register preload amortizes over many centers.    */
/* ------------------------------------------------------------------ */
__global__ void __launch_bounds__(128, 2) mlp_kernel(
    const float* __restrict__ x,
    const float* __restrict__ W1, const float* __restrict__ b1,
    const float* __restrict__ W2, const float* __restrict__ b2,
    float* __restrict__ out)
{
    __shared__ float sW1[16][64];
    __shared__ float sb1[64];
    __shared__ float sh[2][32][68];        /* padded rows, 16B-aligned */
    __shared__ int   s_nv[2];
    __shared__ int   s_nbr[2][32];
    __shared__ float s_cpos[2][3];

    const int t    = threadIdx.x;
    const int g    = t >> 6;               /* which center of the pair   */
    const int tp   = t & 63;               /* channel-pair id (0..63)    */
    const int kk   = (t >> 1) & 31;        /* neighbor for layer 1       */
    const int half = t & 1;                /* 32-channel half in layer 1 */

    for (int i = t; i < 16*64; i += 128) sW1[i >> 6][i & 63] = W1[i];
    if (t < 64) sb1[t] = b1[t];

    float2 w2r[64];
#pragma unroll
    for (int j = 0; j < 64; j++)
        w2r[j] = *(const float2*)(W2 + j*128 + tp*2);
    const float2 b2v = *(const float2*)(b2 + tp*2);

    for (int pair = blockIdx.x; pair < NPAIR; pair += gridDim.x) {
        const int c = pair*2 + g;
        const int b = c >> 11;

        __syncthreads();                   /* protect sh/s_* reuse */
        if (t < 2) {
            int cc = pair*2 + t;
            s_nv[t] = g_nvalid[cc];
            int ci  = g_fps_idx[cc];
            int bb  = cc >> 11;
            s_cpos[t][0] = g_px[bb*N + ci];
            s_cpos[t][1] = g_py[bb*N + ci];
            s_cpos[t][2] = g_pz[bb*N + ci];
        }
        if (t < 64) {
            int cc = pair*2 + (t >> 5);
            s_nbr[t >> 5][t & 31] = g_nbr[cc*K + (t & 31)];
        }
        __syncthreads();

        /* ---------- layer 1: feat(16) @ W1 -> relu -> sh ---------- */
        const int n  = s_nbr[g][kk];
        const int bn = b*N + n;
        float feat[16];
        const float* xr = x + (size_t)bn * D_INF;
#pragma unroll
        for (int j = 0; j < D_INF; j++) feat[j] = xr[j];
        feat[13] = g_px[bn] - s_cpos[g][0];
        feat[14] = g_py[bn] - s_cpos[g][1];
        feat[15] = g_pz[bn] - s_cpos[g][2];

#pragma unroll
        for (int ph = 0; ph < 2; ph++) {
            const int cbase = half*32 + ph*16;
            float hacc[16];
#pragma unroll
            for (int c2 = 0; c2 < 16; c2++) hacc[c2] = sb1[cbase + c2];
#pragma unroll
            for (int j = 0; j < 16; j++) {
                float f = feat[j];
#pragma unroll
                for (int c2 = 0; c2 < 16; c2++)
                    hacc[c2] = fmaf(f, sW1[j][cbase + c2], hacc[c2]);
            }
#pragma unroll
            for (int c2 = 0; c2 < 16; c2 += 4) {
                float4 v;
                v.x = fmaxf(hacc[c2+0], 0.f);
                v.y = fmaxf(hacc[c2+1], 0.f);
                v.z = fmaxf(hacc[c2+2], 0.f);
                v.w = fmaxf(hacc[c2+3], 0.f);
                *(float4*)&sh[g][kk][cbase + c2] = v;
            }
        }
        __syncthreads();

        /* ---------- layer 2: h @ W2 -> max over valid k -> relu ---- */
        const int nv = s_nv[g];
        float m0 = -3.4e38f, m1 = -3.4e38f;
        for (int k = 0; k < nv; k++) {
            const float* hr = sh[g][k];
            float d0a = 0.f, d0b = 0.f, d1a = 0.f, d1b = 0.f;
#pragma unroll
            for (int j = 0; j < 64; j += 4) {
                float4 hv = *(const float4*)(hr + j);
                d0a = fmaf(hv.x, w2r[j+0].x, d0a); d1a = fmaf(hv.x, w2r[j+0].y, d1a);
                d0b = fmaf(hv.y, w2r[j+1].x, d0b); d1b = fmaf(hv.y, w2r[j+1].y, d1b);
                d0a = fmaf(hv.z, w2r[j+2].x, d0a); d1a = fmaf(hv.z, w2r[j+2].y, d1a);
                d0b = fmaf(hv.w, w2r[j+3].x, d0b); d1b = fmaf(hv.w, w2r[j+3].y, d1b);
            }
            m0 = fmaxf(m0, d0a + d0b);
            m1 = fmaxf(m1, d1a + d1b);
        }
        /* relu(max_k(dot)+b2) == max_k(relu(dot+b2)) since relu monotone,
           and at least one valid neighbor always exists */
        float2 o;
        o.x = fmaxf(m0 + b2v.x, 0.f);
        o.y = fmaxf(m1 + b2v.y, 0.f);
        *(float2*)(out + X_OFF + (size_t)c*128 + tp*2) = o;
    }
}

/* ------------------------------------------------------------------ */
extern "C" void kernel_launch(void* const* d_in, const int* in_sizes, int n_in,
                              void* d_out, int out_size) {
    const float* x   = (const float*)d_in[0];
    const float* pos = (const float*)d_in[1];
    /* d_in[2] = batch (int32), values are just the batch index: unused */
    const float* W1  = (const float*)d_in[3];
    const float* b1  = (const float*)d_in[4];
    const float* W2  = (const float*)d_in[5];
    const float* b2  = (const float*)d_in[6];
    float* out = (float*)d_out;

    soa_kernel<<<(B*N + 255)/256, 256>>>(pos);
    sort_kernel<<<B, 512>>>();
    fps_kernel<<<B, FPS_T>>>();
    ballquery_kernel<<<(NC*32)/256, 256>>>(out);
    mlp_kernel<<<304, 128>>>(x, W1, b1, W2, b2, out);
}